// round 7
// baseline (speedup 1.0000x reference)
#include <cuda_runtime.h>

// Unitary gate on wires {5,13} of a 26-wire register (target bits 20 and 12).
// out[b + off] = U[4x4] @ x[b + off], off ∈ {0, 2^12, 2^20, 2^20+2^12}.
//
// DRAM-bound streaming kernel, 512 MB total traffic.
// R7 = R6 (vectorized U load, streaming hints, 256-thread blocks)
// + 2 sequential float4-groups per thread with a compiler barrier between
// them, so per-thread overhead halves WITHOUT the R2 register blowup
// (live set stays ~5 vectors; regs target <= 40).

static constexpr unsigned REST    = 1u << 24;   // rest-index count
static constexpr unsigned THREADS = REST / 8;   // 8 consecutive rest positions / thread

static constexpr unsigned OFF12_V4 = (1u << 12) >> 2;  // stream offsets in float4 units
static constexpr unsigned OFF20_V4 = (1u << 20) >> 2;

__global__ __launch_bounds__(256)
void unitary_gate_kernel(const float4* __restrict__ x4,
                         const float4* __restrict__ U4,
                         float4*       __restrict__ o4)
{
    unsigned r  = blockIdx.x * blockDim.x + threadIdx.x;   // 0 .. 2^21-1
    unsigned rr = r << 3;                                  // rest index (multiple of 8)

    // Insert zero bits at positions 12 and 20 of the flat amplitude index:
    //   rr bits [0..11]  -> base bits [0..11]
    //   rr bits [12..18] -> base bits [13..19]
    //   rr bits [19..23] -> base bits [21..25]
    unsigned base = (rr & 0x00000FFFu)
                  | ((rr & 0x0007F000u) << 1)
                  | ((rr & 0x00F80000u) << 2);
    unsigned i0 = base >> 2;  // float4 index (base is a multiple of 8)

    // Gate matrix: 4 x 128-bit broadcast loads (L1/L2-resident).
    float4 u0 = __ldg(U4 + 0);
    float4 u1 = __ldg(U4 + 1);
    float4 u2 = __ldg(U4 + 2);
    float4 u3 = __ldg(U4 + 3);

    #pragma unroll
    for (int g = 0; g < 2; g++) {
        unsigned i = i0 + (unsigned)g;

        // Front-batched streaming loads (MLP=4, evict-first).
        float4 s0 = __ldcs(x4 + i);
        float4 s1 = __ldcs(x4 + i + OFF12_V4);
        float4 s2 = __ldcs(x4 + i + OFF20_V4);
        float4 s3 = __ldcs(x4 + i + OFF20_V4 + OFF12_V4);

        float4 d0, d1, d2, d3;
        d0.x = u0.x*s0.x + u0.y*s1.x + u0.z*s2.x + u0.w*s3.x;
        d0.y = u0.x*s0.y + u0.y*s1.y + u0.z*s2.y + u0.w*s3.y;
        d0.z = u0.x*s0.z + u0.y*s1.z + u0.z*s2.z + u0.w*s3.z;
        d0.w = u0.x*s0.w + u0.y*s1.w + u0.z*s2.w + u0.w*s3.w;

        d1.x = u1.x*s0.x + u1.y*s1.x + u1.z*s2.x + u1.w*s3.x;
        d1.y = u1.x*s0.y + u1.y*s1.y + u1.z*s2.y + u1.w*s3.y;
        d1.z = u1.x*s0.z + u1.y*s1.z + u1.z*s2.z + u1.w*s3.z;
        d1.w = u1.x*s0.w + u1.y*s1.w + u1.z*s2.w + u1.w*s3.w;

        d2.x = u2.x*s0.x + u2.y*s1.x + u2.z*s2.x + u2.w*s3.x;
        d2.y = u2.x*s0.y + u2.y*s1.y + u2.z*s2.y + u2.w*s3.y;
        d2.z = u2.x*s0.z + u2.y*s1.z + u2.z*s2.z + u2.w*s3.z;
        d2.w = u2.x*s0.w + u2.y*s1.w + u2.z*s2.w + u2.w*s3.w;

        d3.x = u3.x*s0.x + u3.y*s1.x + u3.z*s2.x + u3.w*s3.x;
        d3.y = u3.x*s0.y + u3.y*s1.y + u3.z*s2.y + u3.w*s3.y;
        d3.z = u3.x*s0.z + u3.y*s1.z + u3.z*s2.z + u3.w*s3.z;
        d3.w = u3.x*s0.w + u3.y*s1.w + u3.z*s2.w + u3.w*s3.w;

        __stcs(o4 + i,                       d0);
        __stcs(o4 + i + OFF12_V4,            d1);
        __stcs(o4 + i + OFF20_V4,            d2);
        __stcs(o4 + i + OFF20_V4 + OFF12_V4, d3);

        // Compiler-only barrier: keep group-B loads BELOW group-A stores so
        // the live register set stays small (avoid the R2 59-reg blowup).
        asm volatile("" ::: "memory");
    }
}

extern "C" void kernel_launch(void* const* d_in, const int* in_sizes, int n_in,
                              void* d_out, int out_size)
{
    const float* x = (const float*)d_in[0];
    const float* U = (const float*)d_in[1];
    if (n_in >= 2 && in_sizes[0] == 16) {  // defensive: swapped order
        U = (const float*)d_in[0];
        x = (const float*)d_in[1];
    }
    float* out = (float*)d_out;

    const unsigned threads = 256;
    const unsigned blocks  = THREADS / threads;  // 8192
    unitary_gate_kernel<<<blocks, threads>>>(
        (const float4*)x, (const float4*)U, (float4*)out);
}

// round 9
// speedup vs baseline: 1.2756x; 1.2756x over previous
#include <cuda_runtime.h>

// Unitary gate on wires {5,13} of a 26-wire register (target bits 20 and 12).
// out[b + off] = U[4x4] @ x[b + off], off ∈ {0, 2^12, 2^20, 2^20+2^12}.
//
// DRAM-bound streaming kernel, 512 MB total traffic.
// R9 = resubmit of R8 (infra failure last round, no data).
// R6 base (4 x float4 / thread, vectorized U load, __ldcs loads, 32 regs,
// ~82% occ) with stores switched to __stwt (write-through) — the output is
// never re-read, so avoid L2 write-allocate pressure.
// R2/R4/R7 established: do NOT change the 4-loads/thread @ 32-reg structure.

static constexpr unsigned REST    = 1u << 24;   // rest-index count
static constexpr unsigned THREADS = REST / 4;   // 4 consecutive rest positions / thread

static constexpr unsigned OFF12_V4 = (1u << 12) >> 2;  // stream offsets in float4 units
static constexpr unsigned OFF20_V4 = (1u << 20) >> 2;

__global__ __launch_bounds__(256, 8)
void unitary_gate_kernel(const float4* __restrict__ x4,
                         const float4* __restrict__ U4,
                         float4*       __restrict__ o4)
{
    unsigned r  = blockIdx.x * blockDim.x + threadIdx.x;   // 0 .. 2^22-1
    unsigned rr = r << 2;                                  // rest index (multiple of 4)

    // Insert zero bits at positions 12 and 20 of the flat amplitude index:
    //   rr bits [0..11]  -> base bits [0..11]
    //   rr bits [12..18] -> base bits [13..19]
    //   rr bits [19..23] -> base bits [21..25]
    unsigned base = (rr & 0x00000FFFu)
                  | ((rr & 0x0007F000u) << 1)
                  | ((rr & 0x00F80000u) << 2);
    unsigned i0 = base >> 2;  // float4 index (base is a multiple of 4)

    // Gate matrix: 4 x 128-bit broadcast loads (L1/L2-resident).
    float4 u0 = __ldg(U4 + 0);   // row 0
    float4 u1 = __ldg(U4 + 1);   // row 1
    float4 u2 = __ldg(U4 + 2);   // row 2
    float4 u3 = __ldg(U4 + 3);   // row 3

    // Front-batched streaming loads (MLP=4, evict-first).
    float4 s0 = __ldcs(x4 + i0);
    float4 s1 = __ldcs(x4 + i0 + OFF12_V4);
    float4 s2 = __ldcs(x4 + i0 + OFF20_V4);
    float4 s3 = __ldcs(x4 + i0 + OFF20_V4 + OFF12_V4);

    float4 d0, d1, d2, d3;
    d0.x = u0.x*s0.x + u0.y*s1.x + u0.z*s2.x + u0.w*s3.x;
    d0.y = u0.x*s0.y + u0.y*s1.y + u0.z*s2.y + u0.w*s3.y;
    d0.z = u0.x*s0.z + u0.y*s1.z + u0.z*s2.z + u0.w*s3.z;
    d0.w = u0.x*s0.w + u0.y*s1.w + u0.z*s2.w + u0.w*s3.w;

    d1.x = u1.x*s0.x + u1.y*s1.x + u1.z*s2.x + u1.w*s3.x;
    d1.y = u1.x*s0.y + u1.y*s1.y + u1.z*s2.y + u1.w*s3.y;
    d1.z = u1.x*s0.z + u1.y*s1.z + u1.z*s2.z + u1.w*s3.z;
    d1.w = u1.x*s0.w + u1.y*s1.w + u1.z*s2.w + u1.w*s3.w;

    d2.x = u2.x*s0.x + u2.y*s1.x + u2.z*s2.x + u2.w*s3.x;
    d2.y = u2.x*s0.y + u2.y*s1.y + u2.z*s2.y + u2.w*s3.y;
    d2.z = u2.x*s0.z + u2.y*s1.z + u2.z*s2.z + u2.w*s3.z;
    d2.w = u2.x*s0.w + u2.y*s1.w + u2.z*s2.w + u2.w*s3.w;

    d3.x = u3.x*s0.x + u3.y*s1.x + u3.z*s2.x + u3.w*s3.x;
    d3.y = u3.x*s0.y + u3.y*s1.y + u3.z*s2.y + u3.w*s3.y;
    d3.z = u3.x*s0.z + u3.y*s1.z + u3.z*s2.z + u3.w*s3.z;
    d3.w = u3.x*s0.w + u3.y*s1.w + u3.z*s2.w + u3.w*s3.w;

    // Write-through stores: output is never re-read; skip L2 write-allocate.
    __stwt(o4 + i0,                       d0);
    __stwt(o4 + i0 + OFF12_V4,            d1);
    __stwt(o4 + i0 + OFF20_V4,            d2);
    __stwt(o4 + i0 + OFF20_V4 + OFF12_V4, d3);
}

extern "C" void kernel_launch(void* const* d_in, const int* in_sizes, int n_in,
                              void* d_out, int out_size)
{
    const float* x = (const float*)d_in[0];
    const float* U = (const float*)d_in[1];
    if (n_in >= 2 && in_sizes[0] == 16) {  // defensive: swapped order
        U = (const float*)d_in[0];
        x = (const float*)d_in[1];
    }
    float* out = (float*)d_out;

    const unsigned threads = 256;
    const unsigned blocks  = THREADS / threads;  // 16384
    unitary_gate_kernel<<<blocks, threads>>>(
        (const float4*)x, (const float4*)U, (float4*)out);
}

// round 10
// speedup vs baseline: 1.2856x; 1.0078x over previous
#include <cuda_runtime.h>

// Unitary gate on wires {5,13} of a 26-wire register (target bits 20 and 12).
// out[b + off] = U[4x4] @ x[b + off], off ∈ {0, 2^12, 2^20, 2^20+2^12}.
//
// DRAM-bound streaming kernel, 512 MB minimum traffic (read 256 MB + write
// 256 MB, each touched exactly once).
//
// FINAL (R6 locked in): 4 x float4 per thread, vectorized U load (4 x
// LDG.128 broadcast), __ldcs evict-first loads, __stcs stores.
// 32 regs x 2048 threads/SM exactly fills the register file -> max
// occupancy -> max chip-wide outstanding loads. Measured: 73.9 us ncu,
// 6.51 TB/s, DRAM 82.1% active — at the B300 LTS ceiling (~6300 B/cyc).
// Ruled out across R1-R9: wider per-thread unrolling (reg/occ loss),
// persistent grid (reg/occ loss), serialized multi-group (MLP loss),
// __stwt write-through (neutral).

static constexpr unsigned REST    = 1u << 24;   // rest-index count
static constexpr unsigned THREADS = REST / 4;   // 4 consecutive rest positions / thread

static constexpr unsigned OFF12_V4 = (1u << 12) >> 2;  // stream offsets in float4 units
static constexpr unsigned OFF20_V4 = (1u << 20) >> 2;

__global__ __launch_bounds__(256, 8)
void unitary_gate_kernel(const float4* __restrict__ x4,
                         const float4* __restrict__ U4,
                         float4*       __restrict__ o4)
{
    unsigned r  = blockIdx.x * blockDim.x + threadIdx.x;   // 0 .. 2^22-1
    unsigned rr = r << 2;                                  // rest index (multiple of 4)

    // Insert zero bits at positions 12 and 20 of the flat amplitude index:
    //   rr bits [0..11]  -> base bits [0..11]
    //   rr bits [12..18] -> base bits [13..19]
    //   rr bits [19..23] -> base bits [21..25]
    unsigned base = (rr & 0x00000FFFu)
                  | ((rr & 0x0007F000u) << 1)
                  | ((rr & 0x00F80000u) << 2);
    unsigned i0 = base >> 2;  // float4 index (base is a multiple of 4)

    // Gate matrix: 4 x 128-bit broadcast loads (L1/L2-resident).
    float4 u0 = __ldg(U4 + 0);   // row 0
    float4 u1 = __ldg(U4 + 1);   // row 1
    float4 u2 = __ldg(U4 + 2);   // row 2
    float4 u3 = __ldg(U4 + 3);   // row 3

    // Front-batched streaming loads (MLP=4, evict-first).
    float4 s0 = __ldcs(x4 + i0);
    float4 s1 = __ldcs(x4 + i0 + OFF12_V4);
    float4 s2 = __ldcs(x4 + i0 + OFF20_V4);
    float4 s3 = __ldcs(x4 + i0 + OFF20_V4 + OFF12_V4);

    float4 d0, d1, d2, d3;
    d0.x = u0.x*s0.x + u0.y*s1.x + u0.z*s2.x + u0.w*s3.x;
    d0.y = u0.x*s0.y + u0.y*s1.y + u0.z*s2.y + u0.w*s3.y;
    d0.z = u0.x*s0.z + u0.y*s1.z + u0.z*s2.z + u0.w*s3.z;
    d0.w = u0.x*s0.w + u0.y*s1.w + u0.z*s2.w + u0.w*s3.w;

    d1.x = u1.x*s0.x + u1.y*s1.x + u1.z*s2.x + u1.w*s3.x;
    d1.y = u1.x*s0.y + u1.y*s1.y + u1.z*s2.y + u1.w*s3.y;
    d1.z = u1.x*s0.z + u1.y*s1.z + u1.z*s2.z + u1.w*s3.z;
    d1.w = u1.x*s0.w + u1.y*s1.w + u1.z*s2.w + u1.w*s3.w;

    d2.x = u2.x*s0.x + u2.y*s1.x + u2.z*s2.x + u2.w*s3.x;
    d2.y = u2.x*s0.y + u2.y*s1.y + u2.z*s2.y + u2.w*s3.y;
    d2.z = u2.x*s0.z + u2.y*s1.z + u2.z*s2.z + u2.w*s3.z;
    d2.w = u2.x*s0.w + u2.y*s1.w + u2.z*s2.w + u2.w*s3.w;

    d3.x = u3.x*s0.x + u3.y*s1.x + u3.z*s2.x + u3.w*s3.x;
    d3.y = u3.x*s0.y + u3.y*s1.y + u3.z*s2.y + u3.w*s3.y;
    d3.z = u3.x*s0.z + u3.y*s1.z + u3.z*s2.z + u3.w*s3.z;
    d3.w = u3.x*s0.w + u3.y*s1.w + u3.z*s2.w + u3.w*s3.w;

    __stcs(o4 + i0,                       d0);
    __stcs(o4 + i0 + OFF12_V4,            d1);
    __stcs(o4 + i0 + OFF20_V4,            d2);
    __stcs(o4 + i0 + OFF20_V4 + OFF12_V4, d3);
}

extern "C" void kernel_launch(void* const* d_in, const int* in_sizes, int n_in,
                              void* d_out, int out_size)
{
    const float* x = (const float*)d_in[0];
    const float* U = (const float*)d_in[1];
    if (n_in >= 2 && in_sizes[0] == 16) {  // defensive: swapped order
        U = (const float*)d_in[0];
        x = (const float*)d_in[1];
    }
    float* out = (float*)d_out;

    const unsigned threads = 256;
    const unsigned blocks  = THREADS / threads;  // 16384
    unitary_gate_kernel<<<blocks, threads>>>(
        (const float4*)x, (const float4*)U, (float4*)out);
}

// round 11
// speedup vs baseline: 1.3003x; 1.0114x over previous
#include <cuda_runtime.h>

// Unitary gate on wires {5,13} of a 26-wire register (target bits 20 and 12).
// out[b + off] = U[4x4] @ x[b + off], off ∈ {0, 2^12, 2^20, 2^20+2^12}.
//
// DRAM-bound streaming kernel, 512 MB minimum traffic (read 256 MB + write
// 256 MB, each touched exactly once). Measured at the B300 LTS ceiling:
// ~6.5 TB/s, DRAM ~82% active, 32 regs, full-RF occupancy.
//
// R11 = R6 body exactly (4 x float4 / thread, vectorized U broadcast load,
// __ldcs loads, __stcs stores) with BLOCK 256 -> 512: doubles per-stream
// contiguity per block (4 KB -> 8 KB, better DRAM row locality) and halves
// block transitions. Register/occupancy profile unchanged — zero risk of
// the R2/R4/R7 occupancy failures.
// Ruled out across R1-R10: wider unrolling, persistent grid, serialized
// groups, __stwt, scalar U loads.

static constexpr unsigned REST    = 1u << 24;   // rest-index count
static constexpr unsigned THREADS = REST / 4;   // 4 consecutive rest positions / thread

static constexpr unsigned OFF12_V4 = (1u << 12) >> 2;  // stream offsets in float4 units
static constexpr unsigned OFF20_V4 = (1u << 20) >> 2;

static constexpr unsigned BLOCK = 512;

__global__ __launch_bounds__(BLOCK, 4)
void unitary_gate_kernel(const float4* __restrict__ x4,
                         const float4* __restrict__ U4,
                         float4*       __restrict__ o4)
{
    unsigned r  = blockIdx.x * BLOCK + threadIdx.x;        // 0 .. 2^22-1
    unsigned rr = r << 2;                                  // rest index (multiple of 4)

    // Insert zero bits at positions 12 and 20 of the flat amplitude index:
    //   rr bits [0..11]  -> base bits [0..11]
    //   rr bits [12..18] -> base bits [13..19]
    //   rr bits [19..23] -> base bits [21..25]
    unsigned base = (rr & 0x00000FFFu)
                  | ((rr & 0x0007F000u) << 1)
                  | ((rr & 0x00F80000u) << 2);
    unsigned i0 = base >> 2;  // float4 index (base is a multiple of 4)

    // Gate matrix: 4 x 128-bit broadcast loads (L1/L2-resident).
    float4 u0 = __ldg(U4 + 0);   // row 0
    float4 u1 = __ldg(U4 + 1);   // row 1
    float4 u2 = __ldg(U4 + 2);   // row 2
    float4 u3 = __ldg(U4 + 3);   // row 3

    // Front-batched streaming loads (MLP=4, evict-first).
    float4 s0 = __ldcs(x4 + i0);
    float4 s1 = __ldcs(x4 + i0 + OFF12_V4);
    float4 s2 = __ldcs(x4 + i0 + OFF20_V4);
    float4 s3 = __ldcs(x4 + i0 + OFF20_V4 + OFF12_V4);

    float4 d0, d1, d2, d3;
    d0.x = u0.x*s0.x + u0.y*s1.x + u0.z*s2.x + u0.w*s3.x;
    d0.y = u0.x*s0.y + u0.y*s1.y + u0.z*s2.y + u0.w*s3.y;
    d0.z = u0.x*s0.z + u0.y*s1.z + u0.z*s2.z + u0.w*s3.z;
    d0.w = u0.x*s0.w + u0.y*s1.w + u0.z*s2.w + u0.w*s3.w;

    d1.x = u1.x*s0.x + u1.y*s1.x + u1.z*s2.x + u1.w*s3.x;
    d1.y = u1.x*s0.y + u1.y*s1.y + u1.z*s2.y + u1.w*s3.y;
    d1.z = u1.x*s0.z + u1.y*s1.z + u1.z*s2.z + u1.w*s3.z;
    d1.w = u1.x*s0.w + u1.y*s1.w + u1.z*s2.w + u1.w*s3.w;

    d2.x = u2.x*s0.x + u2.y*s1.x + u2.z*s2.x + u2.w*s3.x;
    d2.y = u2.x*s0.y + u2.y*s1.y + u2.z*s2.y + u2.w*s3.y;
    d2.z = u2.x*s0.z + u2.y*s1.z + u2.z*s2.z + u2.w*s3.z;
    d2.w = u2.x*s0.w + u2.y*s1.w + u2.z*s2.w + u2.w*s3.w;

    d3.x = u3.x*s0.x + u3.y*s1.x + u3.z*s2.x + u3.w*s3.x;
    d3.y = u3.x*s0.y + u3.y*s1.y + u3.z*s2.y + u3.w*s3.y;
    d3.z = u3.x*s0.z + u3.y*s1.z + u3.z*s2.z + u3.w*s3.z;
    d3.w = u3.x*s0.w + u3.y*s1.w + u3.z*s2.w + u3.w*s3.w;

    __stcs(o4 + i0,                       d0);
    __stcs(o4 + i0 + OFF12_V4,            d1);
    __stcs(o4 + i0 + OFF20_V4,            d2);
    __stcs(o4 + i0 + OFF20_V4 + OFF12_V4, d3);
}

extern "C" void kernel_launch(void* const* d_in, const int* in_sizes, int n_in,
                              void* d_out, int out_size)
{
    const float* x = (const float*)d_in[0];
    const float* U = (const float*)d_in[1];
    if (n_in >= 2 && in_sizes[0] == 16) {  // defensive: swapped order
        U = (const float*)d_in[0];
        x = (const float*)d_in[1];
    }
    float* out = (float*)d_out;

    const unsigned blocks = THREADS / BLOCK;  // 8192
    unitary_gate_kernel<<<blocks, BLOCK>>>(
        (const float4*)x, (const float4*)U, (float4*)out);
}

// round 13
// speedup vs baseline: 1.3019x; 1.0012x over previous
#include <cuda_runtime.h>

// Unitary gate on wires {5,13} of a 26-wire register (target bits 20 and 12).
// out[b + off] = U[4x4] @ x[b + off], off ∈ {0, 2^12, 2^20, 2^20+2^12}.
//
// DRAM-bound streaming kernel, 512 MB minimum traffic (read + write, each
// touched once). Running at the B300 LTS ceiling (~6.5 TB/s, DRAM ~82.5%).
//
// R12 = R11 body exactly (4 x float4 / thread, vectorized U broadcast load,
// __ldcs loads, __stcs stores, 32 regs) with BLOCK 512 -> 1024: block-size
// gradient won at 256->512 (DRAM 81.7 -> 82.5%, row-burst locality), so take
// one more step. 16 KB contiguity per stream per block; 2 blocks/SM fills
// the RF exactly as before.
// Ruled out R1-R11: wider unrolling, persistent grid, serialized groups,
// __stwt, scalar U loads.

static constexpr unsigned REST    = 1u << 24;   // rest-index count
static constexpr unsigned THREADS = REST / 4;   // 4 consecutive rest positions / thread

static constexpr unsigned OFF12_V4 = (1u << 12) >> 2;  // stream offsets in float4 units
static constexpr unsigned OFF20_V4 = (1u << 20) >> 2;

static constexpr unsigned BLOCK = 1024;

__global__ __launch_bounds__(BLOCK, 2)
void unitary_gate_kernel(const float4* __restrict__ x4,
                         const float4* __restrict__ U4,
                         float4*       __restrict__ o4)
{
    unsigned r  = blockIdx.x * BLOCK + threadIdx.x;        // 0 .. 2^22-1
    unsigned rr = r << 2;                                  // rest index (multiple of 4)

    // Insert zero bits at positions 12 and 20 of the flat amplitude index:
    //   rr bits [0..11]  -> base bits [0..11]
    //   rr bits [12..18] -> base bits [13..19]
    //   rr bits [19..23] -> base bits [21..25]
    unsigned base = (rr & 0x00000FFFu)
                  | ((rr & 0x0007F000u) << 1)
                  | ((rr & 0x00F80000u) << 2);
    unsigned i0 = base >> 2;  // float4 index (base is a multiple of 4)

    // Gate matrix: 4 x 128-bit broadcast loads (L1/L2-resident).
    float4 u0 = __ldg(U4 + 0);   // row 0
    float4 u1 = __ldg(U4 + 1);   // row 1
    float4 u2 = __ldg(U4 + 2);   // row 2
    float4 u3 = __ldg(U4 + 3);   // row 3

    // Front-batched streaming loads (MLP=4, evict-first).
    float4 s0 = __ldcs(x4 + i0);
    float4 s1 = __ldcs(x4 + i0 + OFF12_V4);
    float4 s2 = __ldcs(x4 + i0 + OFF20_V4);
    float4 s3 = __ldcs(x4 + i0 + OFF20_V4 + OFF12_V4);

    float4 d0, d1, d2, d3;
    d0.x = u0.x*s0.x + u0.y*s1.x + u0.z*s2.x + u0.w*s3.x;
    d0.y = u0.x*s0.y + u0.y*s1.y + u0.z*s2.y + u0.w*s3.y;
    d0.z = u0.x*s0.z + u0.y*s1.z + u0.z*s2.z + u0.w*s3.z;
    d0.w = u0.x*s0.w + u0.y*s1.w + u0.z*s2.w + u0.w*s3.w;

    d1.x = u1.x*s0.x + u1.y*s1.x + u1.z*s2.x + u1.w*s3.x;
    d1.y = u1.x*s0.y + u1.y*s1.y + u1.z*s2.y + u1.w*s3.y;
    d1.z = u1.x*s0.z + u1.y*s1.z + u1.z*s2.z + u1.w*s3.z;
    d1.w = u1.x*s0.w + u1.y*s1.w + u1.z*s2.w + u1.w*s3.w;

    d2.x = u2.x*s0.x + u2.y*s1.x + u2.z*s2.x + u2.w*s3.x;
    d2.y = u2.x*s0.y + u2.y*s1.y + u2.z*s2.y + u2.w*s3.y;
    d2.z = u2.x*s0.z + u2.y*s1.z + u2.z*s2.z + u2.w*s3.z;
    d2.w = u2.x*s0.w + u2.y*s1.w + u2.z*s2.w + u2.w*s3.w;

    d3.x = u3.x*s0.x + u3.y*s1.x + u3.z*s2.x + u3.w*s3.x;
    d3.y = u3.x*s0.y + u3.y*s1.y + u3.z*s2.y + u3.w*s3.y;
    d3.z = u3.x*s0.z + u3.y*s1.z + u3.z*s2.z + u3.w*s3.z;
    d3.w = u3.x*s0.w + u3.y*s1.w + u3.z*s2.w + u3.w*s3.w;

    __stcs(o4 + i0,                       d0);
    __stcs(o4 + i0 + OFF12_V4,            d1);
    __stcs(o4 + i0 + OFF20_V4,            d2);
    __stcs(o4 + i0 + OFF20_V4 + OFF12_V4, d3);
}

extern "C" void kernel_launch(void* const* d_in, const int* in_sizes, int n_in,
                              void* d_out, int out_size)
{
    const float* x = (const float*)d_in[0];
    const float* U = (const float*)d_in[1];
    if (n_in >= 2 && in_sizes[0] == 16) {  // defensive: swapped order
        U = (const float*)d_in[0];
        x = (const float*)d_in[1];
    }
    float* out = (float*)d_out;

    const unsigned blocks = THREADS / BLOCK;  // 4096
    unitary_gate_kernel<<<blocks, BLOCK>>>(
        (const float4*)x, (const float4*)U, (float4*)out);
}